// round 3
// baseline (speedup 1.0000x reference)
#include <cuda_runtime.h>
#include <cuda_bf16.h>
#include <cooperative_groups.h>
#include <cstdint>

namespace cg = cooperative_groups;

#define BB 32
#define TT 2048
#define DD 256
#define HH 256
#define G4 1024
#define KK 8

// ---------------- scratch (device globals; no runtime allocation) ----------------
__device__ float g_G[(size_t)2 * BB * TT * G4];    // gate pre-activations, both dirs
__device__ float g_h[(size_t)2 * BB * TT * HH];    // h_f / h_b (backward already un-reversed)
__device__ float g_emis[(size_t)BB * TT * KK];
__device__ float g_res[BB];

// ---------------- Kernel 1: input projection GEMM ----------------
// G[dir][b*T+t][j] = sum_k x[b,t,k]*w_ih_dir[j,k] + b_ih[j] + b_hh[j]
__global__ void __launch_bounds__(256, 3) proj_kernel(
    const float* __restrict__ x,
    const float* __restrict__ wf, const float* __restrict__ bif, const float* __restrict__ bhf,
    const float* __restrict__ wb, const float* __restrict__ bib, const float* __restrict__ bhb)
{
    __shared__ float sA[32 * 132];
    __shared__ float sB[32 * 68];

    const int dir = blockIdx.z;
    const float* w  = dir ? wb  : wf;
    const float* bi = dir ? bib : bif;
    const float* bh = dir ? bhb : bhf;

    const int tid = threadIdx.x;
    const int bM = blockIdx.x * 128;
    const int bN = blockIdx.y * 64;
    const int ty = tid >> 4;
    const int tx = tid & 15;

    float acc[8][4];
#pragma unroll
    for (int i = 0; i < 8; ++i)
#pragma unroll
        for (int c = 0; c < 4; ++c) acc[i][c] = 0.0f;

    const int rowL = tid >> 3;
    const int kL   = (tid & 7) << 2;
    const float* xg = x + (size_t)(bM + rowL) * DD + kL;
    const float* wg = w + (size_t)(bN + rowL) * DD + kL;

    for (int kt = 0; kt < 8; ++kt) {
        const int k0 = kt * 32;
#pragma unroll
        for (int p = 0; p < 4; ++p) {
            float4 v = *(const float4*)(xg + (size_t)p * 32 * DD + k0);
            int m = rowL + p * 32;
            sA[(kL + 0) * 132 + m] = v.x;
            sA[(kL + 1) * 132 + m] = v.y;
            sA[(kL + 2) * 132 + m] = v.z;
            sA[(kL + 3) * 132 + m] = v.w;
        }
#pragma unroll
        for (int p = 0; p < 2; ++p) {
            float4 v = *(const float4*)(wg + (size_t)p * 32 * DD + k0);
            int n = rowL + p * 32;
            sB[(kL + 0) * 68 + n] = v.x;
            sB[(kL + 1) * 68 + n] = v.y;
            sB[(kL + 2) * 68 + n] = v.z;
            sB[(kL + 3) * 68 + n] = v.w;
        }
        __syncthreads();
#pragma unroll
        for (int kk = 0; kk < 32; ++kk) {
            float4 a0 = *(const float4*)&sA[kk * 132 + ty * 8];
            float4 a1 = *(const float4*)&sA[kk * 132 + ty * 8 + 4];
            float4 bv = *(const float4*)&sB[kk * 68 + tx * 4];
            float ar[8] = {a0.x, a0.y, a0.z, a0.w, a1.x, a1.y, a1.z, a1.w};
            float br[4] = {bv.x, bv.y, bv.z, bv.w};
#pragma unroll
            for (int i = 0; i < 8; ++i)
#pragma unroll
                for (int c = 0; c < 4; ++c) acc[i][c] = fmaf(ar[i], br[c], acc[i][c]);
        }
        __syncthreads();
    }

    float bias[4];
#pragma unroll
    for (int c = 0; c < 4; ++c) {
        int j = bN + tx * 4 + c;
        bias[c] = bi[j] + bh[j];
    }
    float* Gd = g_G + (size_t)dir * BB * TT * G4;
#pragma unroll
    for (int i = 0; i < 8; ++i) {
        int m = bM + ty * 8 + i;
        float4 o = make_float4(acc[i][0] + bias[0], acc[i][1] + bias[1],
                               acc[i][2] + bias[2], acc[i][3] + bias[3]);
        *(float4*)(Gd + (size_t)m * G4 + bN + tx * 4) = o;
    }
}

// ---------------- Kernel 2: LSTM recurrence (cluster-persistent) ----------------
// 16 clusters of 8 CTAs: cluster = (dir, 4-batch group). CTA rank r owns hidden
// units [32r,32r+32): gate rows gt*256 + 32r + u. w_hh slice resident in SMEM
// (k-major). h (256 x 4 batch) double-buffered, broadcast via DSMEM each step.
#define REC_SMEM_FLOATS (32768 + 2048 + 512)
#define REC_SMEM_BYTES  (REC_SMEM_FLOATS * 4)

__global__ void __launch_bounds__(128, 1) __cluster_dims__(8, 1, 1)
lstm_rec_kernel(const float* __restrict__ whh_f, const float* __restrict__ whh_b,
                const int* __restrict__ lengths)
{
    extern __shared__ float sm[];
    float* s_w = sm;                 // [256 k][128 g]
    float* s_h = sm + 32768;         // [2 buf][256 k][4 b]
    float* s_g = sm + 32768 + 2048;  // [128 g][4 b]

    cg::cluster_group cluster = cg::this_cluster();
    const int rank = cluster.block_rank();
    const int cidx = blockIdx.x >> 3;
    const int dir  = cidx >> 3;
    const int b0   = (cidx & 7) * 4;
    const int tid  = threadIdx.x;

    const float* whh = dir ? whh_b : whh_f;

    {   // load weight slice transposed to k-major
        const int g = tid;
        const int gt = g >> 5, ul = g & 31;
        const float* wrow = whh + (size_t)((gt << 8) + (rank << 5) + ul) * HH;
#pragma unroll 4
        for (int k4 = 0; k4 < 64; ++k4) {
            float4 v = *(const float4*)(wrow + k4 * 4);
            s_w[(k4 * 4 + 0) * 128 + g] = v.x;
            s_w[(k4 * 4 + 1) * 128 + g] = v.y;
            s_w[(k4 * 4 + 2) * 128 + g] = v.z;
            s_w[(k4 * 4 + 3) * 128 + g] = v.w;
        }
    }
    for (int i = tid; i < 2048; i += 128) s_h[i] = 0.0f;
    __syncthreads();

    int L[4];
#pragma unroll
    for (int b = 0; b < 4; ++b) L[b] = lengths[b0 + b];

    float* rem[8];
#pragma unroll
    for (int r = 0; r < 8; ++r) rem[r] = cluster.map_shared_rank(s_h, r);

    cluster.sync();

    const int g  = tid;
    const int gt = g >> 5, ul = g & 31;
    const int row_g = (gt << 8) + (rank << 5) + ul;

    const int ul2 = tid >> 2;            // update stage: local hidden unit
    const int bu  = tid & 3;             // update stage: batch
    const int ugl = (rank << 5) + ul2;   // global hidden unit
    float c_state = 0.0f;

    const float* Gbase = g_G + (size_t)dir * BB * TT * G4;
    float* hbase = g_h + (size_t)dir * BB * TT * HH;

    int cur = 0;
    for (int s = 0; s < TT; ++s) {
        int tsM[4];
#pragma unroll
        for (int b = 0; b < 4; ++b) tsM[b] = dir ? (s < L[b] ? L[b] - 1 - s : s) : s;

        // prefetch gate pre-activations (consumed after matvec)
        float p0 = Gbase[((size_t)(b0 + 0) * TT + tsM[0]) * G4 + row_g];
        float p1 = Gbase[((size_t)(b0 + 1) * TT + tsM[1]) * G4 + row_g];
        float p2 = Gbase[((size_t)(b0 + 2) * TT + tsM[2]) * G4 + row_g];
        float p3 = Gbase[((size_t)(b0 + 3) * TT + tsM[3]) * G4 + row_g];

        float acc0 = 0.f, acc1 = 0.f, acc2 = 0.f, acc3 = 0.f;
        const float* hc = s_h + (cur << 10);
        const float* wp = s_w + g;
#pragma unroll 8
        for (int k = 0; k < 256; ++k) {
            float w = wp[k << 7];
            float4 h4 = *(const float4*)(hc + (k << 2));
            acc0 = fmaf(w, h4.x, acc0);
            acc1 = fmaf(w, h4.y, acc1);
            acc2 = fmaf(w, h4.z, acc2);
            acc3 = fmaf(w, h4.w, acc3);
        }
        ((float4*)s_g)[g] = make_float4(acc0 + p0, acc1 + p1, acc2 + p2, acc3 + p3);
        __syncthreads();

        {
            float iv = s_g[(0   + ul2) * 4 + bu];
            float fv = s_g[(32  + ul2) * 4 + bu];
            float gv = s_g[(64  + ul2) * 4 + bu];
            float ov = s_g[(96  + ul2) * 4 + bu];
            float si = 1.0f / (1.0f + __expf(-iv));
            float sf = 1.0f / (1.0f + __expf(-fv));
            float so = 1.0f / (1.0f + __expf(-ov));
            float c_new = sf * c_state + si * tanhf(gv);
            float h_new = so * tanhf(c_new);
            c_state = c_new;

            const int nxt = cur ^ 1;
            const int off = (nxt << 10) + (ugl << 2) + bu;
#pragma unroll
            for (int r = 0; r < 8; ++r) rem[r][off] = h_new;

            int tt = dir ? (s < L[bu] ? L[bu] - 1 - s : s) : s;
            hbase[((size_t)(b0 + bu) * TT + tt) * HH + ugl] = h_new;
        }
        cluster.sync();
        cur ^= 1;
    }
}

// ---------------- Kernel 3: emissions ----------------
__global__ void __launch_bounds__(256) emis_kernel(const float* __restrict__ wtag,
                                                   const float* __restrict__ btag)
{
    __shared__ float sw[KK * 512];
    __shared__ float sb[KK];
    for (int i = threadIdx.x; i < KK * 512; i += 256) sw[i] = wtag[i];
    if (threadIdx.x < KK) sb[threadIdx.x] = btag[threadIdx.x];
    __syncthreads();

    const int warp = threadIdx.x >> 5, lane = threadIdx.x & 31;
    const size_t m = (size_t)blockIdx.x * 8 + warp;
    const float* hf = g_h + m * HH;
    const float* hb = g_h + (size_t)BB * TT * HH + m * HH;

    float acc[KK];
#pragma unroll
    for (int k = 0; k < KK; ++k) acc[k] = 0.0f;
#pragma unroll
    for (int i = 0; i < 8; ++i) {
        int idx = lane + i * 32;
        float a = hf[idx], b2 = hb[idx];
#pragma unroll
        for (int k = 0; k < KK; ++k) {
            acc[k] = fmaf(a,  sw[k * 512 + idx],       acc[k]);
            acc[k] = fmaf(b2, sw[k * 512 + 256 + idx], acc[k]);
        }
    }
#pragma unroll
    for (int k = 0; k < KK; ++k) {
        float v = acc[k];
#pragma unroll
        for (int off = 16; off; off >>= 1) v += __shfl_xor_sync(~0u, v, off);
        if (lane == 0) g_emis[m * KK + k] = v + sb[k];
    }
}

// ---------------- Kernel 4: CRF per-batch (one warp per block) ----------------
__global__ void crf_kernel(const int* __restrict__ tags, const int* __restrict__ lengths,
                           const float* __restrict__ start_trans,
                           const float* __restrict__ end_trans,
                           const float* __restrict__ trans)
{
    const int b = blockIdx.x;
    const int lane = threadIdx.x & 31;
    const int L = lengths[b];
    const float* E = g_emis + (size_t)b * TT * KK;
    const int* tg = tags + (size_t)b * TT;
    const int j = lane & 7;

    float tc[KK];
#pragma unroll
    for (int i = 0; i < KK; ++i) tc[i] = trans[i * KK + j];

    float sc = start_trans[j] + E[j];
    float e_nxt = E[KK + j];
    for (int t = 1; t < TT; ++t) {
        float e = e_nxt;
        if (t + 1 < TT) e_nxt = E[(t + 1) * KK + j];
        float s[KK];
#pragma unroll
        for (int i = 0; i < KK; ++i) s[i] = __shfl_sync(~0u, sc, i) + tc[i];
        float mx = s[0];
#pragma unroll
        for (int i = 1; i < KK; ++i) mx = fmaxf(mx, s[i]);
        float sum = 0.0f;
#pragma unroll
        for (int i = 0; i < KK; ++i) sum += expf(s[i] - mx);
        float nxt = mx + logf(sum) + e;
        sc = (t < L) ? nxt : sc;
    }

    // logZ: lse over lanes 0..7 (each group of 8 lanes holds identical copies)
    float z = sc + end_trans[j];
    float mz = z;
#pragma unroll
    for (int off = 4; off; off >>= 1) mz = fmaxf(mz, __shfl_xor_sync(~0u, mz, off));
    float sz = expf(z - mz);
#pragma unroll
    for (int off = 4; off; off >>= 1) sz += __shfl_xor_sync(~0u, sz, off);
    float logZ = mz + logf(sz);

    // numerator (lane-parallel over t)
    float part = 0.0f;
    for (int t = 1 + lane; t < TT; t += 32)
        if (t < L) part += trans[tg[t - 1] * KK + tg[t]] + E[t * KK + tg[t]];
#pragma unroll
    for (int off = 16; off; off >>= 1) part += __shfl_xor_sync(~0u, part, off);

    if (lane == 0) {
        int t0 = tg[0];
        float num = start_trans[t0] + E[t0] + part + end_trans[tg[L - 1]];
        g_res[b] = num - logZ;
    }
}

// ---------------- Kernel 5: finalize ----------------
__global__ void finalize_kernel(float* __restrict__ out)
{
    float v = g_res[threadIdx.x];
#pragma unroll
    for (int off = 16; off; off >>= 1) v += __shfl_xor_sync(~0u, v, off);
    if (threadIdx.x == 0) out[0] = -v / (float)BB;
}

// ---------------- launch ----------------
extern "C" void kernel_launch(void* const* d_in, const int* in_sizes, int n_in,
                              void* d_out, int out_size)
{
    const float* sentences = (const float*)d_in[0];
    const int*   tags      = (const int*)  d_in[1];
    const int*   lengths   = (const int*)  d_in[2];
    // d_in[3] = mask (recomputed from lengths)
    const float* w_ih_f = (const float*)d_in[4];
    const float* w_hh_f = (const float*)d_in[5];
    const float* b_ih_f = (const float*)d_in[6];
    const float* b_hh_f = (const float*)d_in[7];
    const float* w_ih_b = (const float*)d_in[8];
    const float* w_hh_b = (const float*)d_in[9];
    const float* b_ih_b = (const float*)d_in[10];
    const float* b_hh_b = (const float*)d_in[11];
    const float* w_tag  = (const float*)d_in[12];
    const float* b_tag  = (const float*)d_in[13];
    const float* start_trans = (const float*)d_in[14];
    const float* end_trans   = (const float*)d_in[15];
    const float* trans       = (const float*)d_in[16];
    float* out = (float*)d_out;

    cudaFuncSetAttribute(lstm_rec_kernel,
                         cudaFuncAttributeMaxDynamicSharedMemorySize, REC_SMEM_BYTES);

    dim3 pg(512, 16, 2);
    proj_kernel<<<pg, 256>>>(sentences, w_ih_f, b_ih_f, b_hh_f, w_ih_b, b_ih_b, b_hh_b);
    lstm_rec_kernel<<<128, 128, REC_SMEM_BYTES>>>(w_hh_f, w_hh_b, lengths);
    emis_kernel<<<(BB * TT) / 8, 256>>>(w_tag, b_tag);
    crf_kernel<<<BB, 32>>>(tags, lengths, start_trans, end_trans, trans);
    finalize_kernel<<<1, 32>>>(out);
}

// round 4
// speedup vs baseline: 1.1549x; 1.1549x over previous
#include <cuda_runtime.h>
#include <cuda_bf16.h>
#include <cooperative_groups.h>
#include <cstdint>

namespace cg = cooperative_groups;

#define BB 32
#define TT 2048
#define DD 256
#define HH 256
#define G4 1024
#define KK 8

// ---------------- scratch (device globals; no runtime allocation) ----------------
__device__ float g_G[(size_t)2 * BB * TT * G4];    // gate pre-activations, both dirs
__device__ float g_h[(size_t)2 * BB * TT * HH];    // h_f / h_b (backward already un-reversed)
__device__ float g_emis[(size_t)BB * TT * KK];
__device__ float g_res[BB];

__device__ __forceinline__ uint32_t cvta_s(const void* p) {
    return (uint32_t)__cvta_generic_to_shared(p);
}

// packed f32x2 helpers (Blackwell FFMA2 path — only via PTX fma.rn.f32x2)
#define FMA2(acc, a, b) asm("fma.rn.f32x2 %0, %1, %2, %0;" : "+l"(acc) : "l"(a), "l"(b))
#define PACK2(d, s)     asm("mov.b64 %0, {%1, %1};" : "=l"(d) : "f"(s))
#define UNPACK2(lo, hi, v) asm("mov.b64 {%0, %1}, %2;" : "=f"(lo), "=f"(hi) : "l"(v))
#define LDS_V2U64(a, b, addr) \
    asm("ld.shared.v2.b64 {%0, %1}, [%2];" : "=l"(a), "=l"(b) : "r"(addr))
#define LDS_V4F32(w0, w1, w2, w3, addr) \
    asm("ld.shared.v4.f32 {%0, %1, %2, %3}, [%4];" \
        : "=f"(w0), "=f"(w1), "=f"(w2), "=f"(w3) : "r"(addr))

__device__ __forceinline__ float sigf(float x)   { return 1.0f / (1.0f + __expf(-x)); }
__device__ __forceinline__ float tanhf2(float x) { return 2.0f / (1.0f + __expf(-2.0f * x)) - 1.0f; }

// ---------------- Kernel 1: input projection GEMM (f32x2) ----------------
// G[dir][b*T+t][j] = sum_k x[b,t,k]*w_ih_dir[j,k] + b_ih[j] + b_hh[j]
__global__ void __launch_bounds__(256, 3) proj_kernel(
    const float* __restrict__ x,
    const float* __restrict__ wf, const float* __restrict__ bif, const float* __restrict__ bhf,
    const float* __restrict__ wb, const float* __restrict__ bib, const float* __restrict__ bhb)
{
    __shared__ float sA[32 * 132];
    __shared__ float sB[32 * 68];

    const int dir = blockIdx.z;
    const float* w  = dir ? wb  : wf;
    const float* bi = dir ? bib : bif;
    const float* bh = dir ? bhb : bhf;

    const int tid = threadIdx.x;
    const int bM = blockIdx.x * 128;
    const int bN = blockIdx.y * 64;
    const int ty = tid >> 4;
    const int tx = tid & 15;

    unsigned long long acc[8][2];
#pragma unroll
    for (int i = 0; i < 8; ++i) { acc[i][0] = 0ull; acc[i][1] = 0ull; }

    const int rowL = tid >> 3;
    const int kL   = (tid & 7) << 2;
    const float* xg = x + (size_t)(bM + rowL) * DD + kL;
    const float* wg = w + (size_t)(bN + rowL) * DD + kL;

    const uint32_t sAa = cvta_s(sA) + ty * 32;          // ty*8 floats
    const uint32_t sBa = cvta_s(sB) + tx * 16;          // tx*4 floats

    for (int kt = 0; kt < 8; ++kt) {
        const int k0 = kt * 32;
#pragma unroll
        for (int p = 0; p < 4; ++p) {
            float4 v = *(const float4*)(xg + (size_t)p * 32 * DD + k0);
            int m = rowL + p * 32;
            sA[(kL + 0) * 132 + m] = v.x;
            sA[(kL + 1) * 132 + m] = v.y;
            sA[(kL + 2) * 132 + m] = v.z;
            sA[(kL + 3) * 132 + m] = v.w;
        }
#pragma unroll
        for (int p = 0; p < 2; ++p) {
            float4 v = *(const float4*)(wg + (size_t)p * 32 * DD + k0);
            int n = rowL + p * 32;
            sB[(kL + 0) * 68 + n] = v.x;
            sB[(kL + 1) * 68 + n] = v.y;
            sB[(kL + 2) * 68 + n] = v.z;
            sB[(kL + 3) * 68 + n] = v.w;
        }
        __syncthreads();
#pragma unroll
        for (int kk = 0; kk < 32; ++kk) {
            float a0, a1, a2, a3, a4, a5, a6, a7;
            LDS_V4F32(a0, a1, a2, a3, sAa + kk * 528);
            LDS_V4F32(a4, a5, a6, a7, sAa + kk * 528 + 16);
            unsigned long long b01, b23;
            LDS_V2U64(b01, b23, sBa + kk * 272);
            unsigned long long aa;
            PACK2(aa, a0); FMA2(acc[0][0], aa, b01); FMA2(acc[0][1], aa, b23);
            PACK2(aa, a1); FMA2(acc[1][0], aa, b01); FMA2(acc[1][1], aa, b23);
            PACK2(aa, a2); FMA2(acc[2][0], aa, b01); FMA2(acc[2][1], aa, b23);
            PACK2(aa, a3); FMA2(acc[3][0], aa, b01); FMA2(acc[3][1], aa, b23);
            PACK2(aa, a4); FMA2(acc[4][0], aa, b01); FMA2(acc[4][1], aa, b23);
            PACK2(aa, a5); FMA2(acc[5][0], aa, b01); FMA2(acc[5][1], aa, b23);
            PACK2(aa, a6); FMA2(acc[6][0], aa, b01); FMA2(acc[6][1], aa, b23);
            PACK2(aa, a7); FMA2(acc[7][0], aa, b01); FMA2(acc[7][1], aa, b23);
        }
        __syncthreads();
    }

    float bias[4];
#pragma unroll
    for (int c = 0; c < 4; ++c) {
        int j = bN + tx * 4 + c;
        bias[c] = bi[j] + bh[j];
    }
    float* Gd = g_G + (size_t)dir * BB * TT * G4;
#pragma unroll
    for (int i = 0; i < 8; ++i) {
        int m = bM + ty * 8 + i;
        float c0, c1, c2, c3;
        UNPACK2(c0, c1, acc[i][0]);
        UNPACK2(c2, c3, acc[i][1]);
        float4 o = make_float4(c0 + bias[0], c1 + bias[1], c2 + bias[2], c3 + bias[3]);
        *(float4*)(Gd + (size_t)m * G4 + bN + tx * 4) = o;
    }
}

// ---------------- Kernel 2: LSTM recurrence (cluster-persistent, f32x2) ----------------
// 16 clusters of 8 CTAs: cluster = (dir, 4-batch group). CTA rank r owns hidden
// units [32r,32r+32): gate rows gt*256 + 32r + u. w_hh slice resident in SMEM
// ([k4][g][4] layout). h (256 x 4 batch) double-buffered, broadcast via DSMEM.
#define REC_SMEM_FLOATS (32768 + 2048 + 512)
#define REC_SMEM_BYTES  (REC_SMEM_FLOATS * 4)

__global__ void __launch_bounds__(128, 1) __cluster_dims__(8, 1, 1)
lstm_rec_kernel(const float* __restrict__ whh_f, const float* __restrict__ whh_b,
                const int* __restrict__ lengths)
{
    extern __shared__ float sm[];
    float* s_w = sm;                 // [64 k4][128 g][4]
    float* s_h = sm + 32768;         // [2 buf][256 k][4 b]
    float* s_g = sm + 32768 + 2048;  // [128 g][4 b]

    cg::cluster_group cluster = cg::this_cluster();
    const int rank = cluster.block_rank();
    const int cidx = blockIdx.x >> 3;
    const int dir  = cidx >> 3;
    const int b0   = (cidx & 7) * 4;
    const int tid  = threadIdx.x;

    const float* whh = dir ? whh_b : whh_f;

    {   // load weight slice into [k4][g][4] layout
        const int g = tid;
        const int gt = g >> 5, ul = g & 31;
        const float* wrow = whh + (size_t)((gt << 8) + (rank << 5) + ul) * HH;
#pragma unroll 4
        for (int k4 = 0; k4 < 64; ++k4) {
            float4 v = *(const float4*)(wrow + k4 * 4);
            *(float4*)(s_w + (size_t)((k4 << 7) + g) * 4) = v;
        }
    }
    for (int i = tid; i < 2048; i += 128) s_h[i] = 0.0f;
    __syncthreads();

    int L[4];
#pragma unroll
    for (int b = 0; b < 4; ++b) L[b] = lengths[b0 + b];

    float* rem[8];
#pragma unroll
    for (int r = 0; r < 8; ++r) rem[r] = cluster.map_shared_rank(s_h, r);

    cluster.sync();

    const int g  = tid;
    const int gt = g >> 5, ul = g & 31;
    const int row_g = (gt << 8) + (rank << 5) + ul;

    const int ul2 = tid >> 2;            // update stage: local hidden unit
    const int bu  = tid & 3;             // update stage: batch
    const int ugl = (rank << 5) + ul2;   // global hidden unit
    float c_state = 0.0f;

    const float* Gbase = g_G + (size_t)dir * BB * TT * G4;
    float* hbase = g_h + (size_t)dir * BB * TT * HH;

    const uint32_t wbase0 = cvta_s(s_w) + tid * 16;
    const uint32_t hbase_s = cvta_s(s_h);

    int cur = 0;
    for (int s = 0; s < TT; ++s) {
        int tsM[4];
#pragma unroll
        for (int b = 0; b < 4; ++b) tsM[b] = dir ? (s < L[b] ? L[b] - 1 - s : s) : s;

        // prefetch gate pre-activations (consumed after matvec)
        float p0 = Gbase[((size_t)(b0 + 0) * TT + tsM[0]) * G4 + row_g];
        float p1 = Gbase[((size_t)(b0 + 1) * TT + tsM[1]) * G4 + row_g];
        float p2 = Gbase[((size_t)(b0 + 2) * TT + tsM[2]) * G4 + row_g];
        float p3 = Gbase[((size_t)(b0 + 3) * TT + tsM[3]) * G4 + row_g];

        unsigned long long acc01 = 0ull, acc23 = 0ull;
        uint32_t wa = wbase0;
        uint32_t ha = hbase_s + (cur << 12);
#pragma unroll 8
        for (int k4 = 0; k4 < 64; ++k4) {
            float w0, w1, w2, w3;
            LDS_V4F32(w0, w1, w2, w3, wa);
            unsigned long long hA0, hA1, hB0, hB1, hC0, hC1, hD0, hD1;
            LDS_V2U64(hA0, hA1, ha);
            LDS_V2U64(hB0, hB1, ha + 16);
            LDS_V2U64(hC0, hC1, ha + 32);
            LDS_V2U64(hD0, hD1, ha + 48);
            unsigned long long wd;
            PACK2(wd, w0); FMA2(acc01, wd, hA0); FMA2(acc23, wd, hA1);
            PACK2(wd, w1); FMA2(acc01, wd, hB0); FMA2(acc23, wd, hB1);
            PACK2(wd, w2); FMA2(acc01, wd, hC0); FMA2(acc23, wd, hC1);
            PACK2(wd, w3); FMA2(acc01, wd, hD0); FMA2(acc23, wd, hD1);
            wa += 2048;   // 128 g * 16 B
            ha += 64;     // 4 k * 16 B
        }
        float a0, a1, a2, a3;
        UNPACK2(a0, a1, acc01);
        UNPACK2(a2, a3, acc23);
        ((float4*)s_g)[g] = make_float4(a0 + p0, a1 + p1, a2 + p2, a3 + p3);
        __syncthreads();

        {
            float iv = s_g[(0   + ul2) * 4 + bu];
            float fv = s_g[(32  + ul2) * 4 + bu];
            float gv = s_g[(64  + ul2) * 4 + bu];
            float ov = s_g[(96  + ul2) * 4 + bu];
            float c_new = sigf(fv) * c_state + sigf(iv) * tanhf2(gv);
            float h_new = sigf(ov) * tanhf2(c_new);
            c_state = c_new;

            const int nxt = cur ^ 1;
            const int off = (nxt << 10) + (ugl << 2) + bu;
#pragma unroll
            for (int r = 0; r < 8; ++r) rem[r][off] = h_new;

            asm volatile("barrier.cluster.arrive.aligned;" ::: "memory");

            int tt = dir ? (s < L[bu] ? L[bu] - 1 - s : s) : s;
            hbase[((size_t)(b0 + bu) * TT + tt) * HH + ugl] = h_new;
        }
        asm volatile("barrier.cluster.wait.aligned;" ::: "memory");
        cur ^= 1;
    }
}

// ---------------- Kernel 3: emissions ----------------
__global__ void __launch_bounds__(256) emis_kernel(const float* __restrict__ wtag,
                                                   const float* __restrict__ btag)
{
    __shared__ float sw[KK * 512];
    __shared__ float sb[KK];
    for (int i = threadIdx.x; i < KK * 512; i += 256) sw[i] = wtag[i];
    if (threadIdx.x < KK) sb[threadIdx.x] = btag[threadIdx.x];
    __syncthreads();

    const int warp = threadIdx.x >> 5, lane = threadIdx.x & 31;
    const size_t m = (size_t)blockIdx.x * 8 + warp;
    const float* hf = g_h + m * HH;
    const float* hb = g_h + (size_t)BB * TT * HH + m * HH;

    float acc[KK];
#pragma unroll
    for (int k = 0; k < KK; ++k) acc[k] = 0.0f;
#pragma unroll
    for (int i = 0; i < 8; ++i) {
        int idx = lane + i * 32;
        float a = hf[idx], b2 = hb[idx];
#pragma unroll
        for (int k = 0; k < KK; ++k) {
            acc[k] = fmaf(a,  sw[k * 512 + idx],       acc[k]);
            acc[k] = fmaf(b2, sw[k * 512 + 256 + idx], acc[k]);
        }
    }
#pragma unroll
    for (int k = 0; k < KK; ++k) {
        float v = acc[k];
#pragma unroll
        for (int off = 16; off; off >>= 1) v += __shfl_xor_sync(~0u, v, off);
        if (lane == 0) g_emis[m * KK + k] = v + sb[k];
    }
}

// ---------------- Kernel 4: CRF per-batch (one warp; lse split over 4 lane-groups) ----------------
__global__ void crf_kernel(const int* __restrict__ tags, const int* __restrict__ lengths,
                           const float* __restrict__ start_trans,
                           const float* __restrict__ end_trans,
                           const float* __restrict__ trans)
{
    const int b = blockIdx.x;
    const int lane = threadIdx.x & 31;
    const int L = lengths[b];
    const float* E = g_emis + (size_t)b * TT * KK;
    const int* tg = tags + (size_t)b * TT;
    const int j  = lane & 7;
    const int i0 = (lane >> 3) * 2;
    const int i1 = i0 + 1;

    const float tc0 = trans[i0 * KK + j];
    const float tc1 = trans[i1 * KK + j];

    float sc = start_trans[j] + E[j];
    float e_nxt = E[KK + j];
    for (int t = 1; t < TT; ++t) {
        float e = e_nxt;
        if (t + 1 < TT) e_nxt = E[(t + 1) * KK + j];
        float s0 = __shfl_sync(~0u, sc, i0) + tc0;
        float s1 = __shfl_sync(~0u, sc, i1) + tc1;
        float m = fmaxf(s0, s1);
        m = fmaxf(m, __shfl_xor_sync(~0u, m, 8));
        m = fmaxf(m, __shfl_xor_sync(~0u, m, 16));
        float p = __expf(s0 - m) + __expf(s1 - m);
        p += __shfl_xor_sync(~0u, p, 8);
        p += __shfl_xor_sync(~0u, p, 16);
        float nxt = m + __logf(p) + e;
        sc = (t < L) ? nxt : sc;
    }

    // logZ: lse over the 8 states (lanes replicated across the 4 groups)
    float z = sc + end_trans[j];
    float mz = z;
#pragma unroll
    for (int off = 4; off; off >>= 1) mz = fmaxf(mz, __shfl_xor_sync(~0u, mz, off));
    float sz = __expf(z - mz);
#pragma unroll
    for (int off = 4; off; off >>= 1) sz += __shfl_xor_sync(~0u, sz, off);
    float logZ = mz + __logf(sz);

    // numerator (lane-parallel over t)
    float part = 0.0f;
    for (int t = 1 + lane; t < TT; t += 32)
        if (t < L) part += trans[tg[t - 1] * KK + tg[t]] + E[t * KK + tg[t]];
#pragma unroll
    for (int off = 16; off; off >>= 1) part += __shfl_xor_sync(~0u, part, off);

    if (lane == 0) {
        int t0 = tg[0];
        float num = start_trans[t0] + E[t0] + part + end_trans[tg[L - 1]];
        g_res[b] = num - logZ;
    }
}

// ---------------- Kernel 5: finalize ----------------
__global__ void finalize_kernel(float* __restrict__ out)
{
    float v = g_res[threadIdx.x];
#pragma unroll
    for (int off = 16; off; off >>= 1) v += __shfl_xor_sync(~0u, v, off);
    if (threadIdx.x == 0) out[0] = -v / (float)BB;
}

// ---------------- launch ----------------
extern "C" void kernel_launch(void* const* d_in, const int* in_sizes, int n_in,
                              void* d_out, int out_size)
{
    const float* sentences = (const float*)d_in[0];
    const int*   tags      = (const int*)  d_in[1];
    const int*   lengths   = (const int*)  d_in[2];
    // d_in[3] = mask (recomputed from lengths)
    const float* w_ih_f = (const float*)d_in[4];
    const float* w_hh_f = (const float*)d_in[5];
    const float* b_ih_f = (const float*)d_in[6];
    const float* b_hh_f = (const float*)d_in[7];
    const float* w_ih_b = (const float*)d_in[8];
    const float* w_hh_b = (const float*)d_in[9];
    const float* b_ih_b = (const float*)d_in[10];
    const float* b_hh_b = (const float*)d_in[11];
    const float* w_tag  = (const float*)d_in[12];
    const float* b_tag  = (const float*)d_in[13];
    const float* start_trans = (const float*)d_in[14];
    const float* end_trans   = (const float*)d_in[15];
    const float* trans       = (const float*)d_in[16];
    float* out = (float*)d_out;

    cudaFuncSetAttribute(lstm_rec_kernel,
                         cudaFuncAttributeMaxDynamicSharedMemorySize, REC_SMEM_BYTES);

    dim3 pg(512, 16, 2);
    proj_kernel<<<pg, 256>>>(sentences, w_ih_f, b_ih_f, b_hh_f, w_ih_b, b_ih_b, b_hh_b);
    lstm_rec_kernel<<<128, 128, REC_SMEM_BYTES>>>(w_hh_f, w_hh_b, lengths);
    emis_kernel<<<(BB * TT) / 8, 256>>>(w_tag, b_tag);
    crf_kernel<<<BB, 32>>>(tags, lengths, start_trans, end_trans, trans);
    finalize_kernel<<<1, 32>>>(out);
}